// round 4
// baseline (speedup 1.0000x reference)
#include <cuda_runtime.h>

#define N_NODES 100000
#define N_EDGES 1600000
#define IN_C 128
#define OUT_C 64

#define SCAN_BLOCK 1024
#define N_SCAN_BLOCKS ((N_NODES + SCAN_BLOCK - 1) / SCAN_BLOCK)   // 98

// ------------------------- device scratch (no alloc allowed) ----------------
__device__ float g_h[N_NODES * OUT_C];     // 25.6 MB (L2-resident)
__device__ int   g_degs[2 * N_NODES];      // [0,N): deg_out   [N,2N): deg_in
__device__ int   g_row_start[N_NODES];     // excl scan of deg_in; after fill = row END
__device__ int   g_esrc[N_EDGES];          // src indices grouped by dst
__device__ int   g_bsum[N_SCAN_BLOCKS];

// ---------------------------------------------------------------------------
// 1) degree counting — int4-vectorized, streaming index reads
// ---------------------------------------------------------------------------
__global__ __launch_bounds__(256) void degree_kernel(const int4* __restrict__ src4,
                                                     const int4* __restrict__ dst4) {
    int i = blockIdx.x * blockDim.x + threadIdx.x;
    if (i < N_EDGES / 4) {
        int4 s = __ldcs(&src4[i]);
        int4 d = __ldcs(&dst4[i]);
        atomicAdd(&g_degs[s.x], 1);
        atomicAdd(&g_degs[s.y], 1);
        atomicAdd(&g_degs[s.z], 1);
        atomicAdd(&g_degs[s.w], 1);
        atomicAdd(&g_degs[N_NODES + d.x], 1);
        atomicAdd(&g_degs[N_NODES + d.y], 1);
        atomicAdd(&g_degs[N_NODES + d.z], 1);
        atomicAdd(&g_degs[N_NODES + d.w], 1);
    }
}

// ---------------------------------------------------------------------------
// 2) block-level scan of deg_in -> chunk-local exclusive prefix + block totals
// ---------------------------------------------------------------------------
__global__ __launch_bounds__(SCAN_BLOCK) void scan_block_kernel() {
    __shared__ int sh[SCAN_BLOCK];
    int t = threadIdx.x;
    int i = blockIdx.x * SCAN_BLOCK + t;
    int v = (i < N_NODES) ? g_degs[N_NODES + i] : 0;
    sh[t] = v;
    __syncthreads();
    #pragma unroll
    for (int off = 1; off < SCAN_BLOCK; off <<= 1) {
        int add = (t >= off) ? sh[t - off] : 0;
        __syncthreads();
        sh[t] += add;
        __syncthreads();
    }
    if (i < N_NODES) g_row_start[i] = sh[t] - v;   // exclusive (chunk-local)
    if (t == SCAN_BLOCK - 1) g_bsum[blockIdx.x] = sh[t];
}

// ---------------------------------------------------------------------------
// 3) every block scans the 98 block-sums in smem and adds its offset.
// ---------------------------------------------------------------------------
__global__ __launch_bounds__(SCAN_BLOCK) void add_offsets_kernel() {
    __shared__ int sh[128];
    int t = threadIdx.x;
    if (t < 128) sh[t] = (t < N_SCAN_BLOCKS) ? g_bsum[t] : 0;
    __syncthreads();
    #pragma unroll
    for (int off = 1; off < 128; off <<= 1) {
        int add = (t < 128 && t >= off) ? sh[t - off] : 0;
        __syncthreads();
        if (t < 128) sh[t] += add;
        __syncthreads();
    }
    int i = blockIdx.x * SCAN_BLOCK + t;
    if (i < N_NODES) {
        int excl = sh[blockIdx.x] - g_bsum[blockIdx.x];  // inclusive - own = exclusive
        g_row_start[i] += excl;
    }
}

// ---------------------------------------------------------------------------
// 4) CSR fill: group src indices by dst.  g_row_start doubles as the cursor;
//    after this kernel g_row_start[d] == row END of d.
// ---------------------------------------------------------------------------
__global__ __launch_bounds__(256) void csr_fill_kernel(const int4* __restrict__ src4,
                                                       const int4* __restrict__ dst4) {
    int i = blockIdx.x * blockDim.x + threadIdx.x;
    if (i < N_EDGES / 4) {
        int4 s = __ldcs(&src4[i]);
        int4 d = __ldcs(&dst4[i]);
        g_esrc[atomicAdd(&g_row_start[d.x], 1)] = s.x;
        g_esrc[atomicAdd(&g_row_start[d.y], 1)] = s.y;
        g_esrc[atomicAdd(&g_row_start[d.z], 1)] = s.z;
        g_esrc[atomicAdd(&g_row_start[d.w], 1)] = s.w;
    }
}

// ---------------------------------------------------------------------------
// 5) GEMM: h = (x * norm_src) @ W   via packed fma.rn.f32x2
//    2 threads per node (32 output cols each) -> 16 f32x2 accumulators = 32
//    regs, 3 blocks/SM (24 warps) to hide LDS latency. 128 nodes per block.
// ---------------------------------------------------------------------------
__global__ __launch_bounds__(256, 3) void gemm_kernel(const float* __restrict__ x,
                                                      const float* __restrict__ w) {
    __shared__ __align__(16) float ws[32 * OUT_C];     // 8 KB  (k-chunk of W)
    __shared__ float xs[32][129];                      // 16.5 KB (k-chunk of x, transposed)

    const int t = threadIdx.x;
    const int nl = t >> 1;               // node-in-block 0..127
    const int half = t & 1;              // which 32-col half
    const int nbase = blockIdx.x * 128;
    const int node = nbase + nl;

    unsigned long long acc[16];
    #pragma unroll
    for (int c = 0; c < 16; c++) acc[c] = 0ULL;

    for (int kc = 0; kc < 4; kc++) {
        __syncthreads();
        // stage W chunk [32 x 64] (coalesced, 8 floats/thread)
        #pragma unroll
        for (int j = 0; j < 8; j++)
            ws[t + 256 * j] = w[(kc * 32) * OUT_C + t + 256 * j];
        // stage x chunk [128 nodes x 32 k] transposed (16 floats/thread)
        #pragma unroll
        for (int j = 0; j < 16; j++) {
            int i = t + 256 * j;
            int n2 = i >> 5;
            int kk = i & 31;
            int nd = nbase + n2;
            float v = (nd < N_NODES) ? __ldcs(&x[nd * IN_C + kc * 32 + kk]) : 0.0f;
            xs[kk][n2] = v;
        }
        __syncthreads();

        #pragma unroll
        for (int kk = 0; kk < 32; kk++) {
            float xv = xs[kk][nl];       // lane pairs broadcast, conflict-free
            unsigned long long xv2;
            asm("mov.b64 %0, {%1, %1};" : "=l"(xv2) : "r"(__float_as_uint(xv)));
            const ulonglong2* wrow = (const ulonglong2*)&ws[kk * OUT_C + half * 32];
            #pragma unroll
            for (int c = 0; c < 8; c++) {
                ulonglong2 w2 = wrow[c];   // LDS.128, broadcast across half-warp
                asm("fma.rn.f32x2 %0, %1, %2, %0;" : "+l"(acc[2 * c])     : "l"(xv2), "l"(w2.x));
                asm("fma.rn.f32x2 %0, %1, %2, %0;" : "+l"(acc[2 * c + 1]) : "l"(xv2), "l"(w2.y));
            }
        }
    }

    if (node < N_NODES) {
        float rn = rsqrtf(fmaxf((float)g_degs[node], 1.0f));
        float* hp = &g_h[node * OUT_C + half * 32];
        #pragma unroll
        for (int c = 0; c < 8; c++) {
            unsigned int l0, h0, l1, h1;
            asm("mov.b64 {%0, %1}, %2;" : "=r"(l0), "=r"(h0) : "l"(acc[2 * c]));
            asm("mov.b64 {%0, %1}, %2;" : "=r"(l1), "=r"(h1) : "l"(acc[2 * c + 1]));
            float4 v;
            v.x = __uint_as_float(l0) * rn;
            v.y = __uint_as_float(h0) * rn;
            v.z = __uint_as_float(l1) * rn;
            v.w = __uint_as_float(h1) * rn;
            *(float4*)&hp[c * 4] = v;
        }
    }
}

// ---------------------------------------------------------------------------
// 6) pull aggregation: out[n] = norm_dst[n] * sum h[src_e] + bias
// ---------------------------------------------------------------------------
__global__ __launch_bounds__(256) void aggregate_kernel(const float4* __restrict__ bias4,
                                                        float* __restrict__ out) {
    int gwarp = (blockIdx.x * 256 + threadIdx.x) >> 5;
    int lane  = threadIdx.x & 31;
    int node  = gwarp * 2 + (lane >> 4);
    if (node >= N_NODES) return;
    int g = lane & 15;

    int cnt = g_degs[N_NODES + node];
    int start = g_row_start[node] - cnt;     // row_start was bumped to END by fill
    const int* ep = &g_esrc[start];

    float4 acc = make_float4(0.f, 0.f, 0.f, 0.f);
    int j = 0;
    for (; j + 8 <= cnt; j += 8) {
        int s0 = ep[j],     s1 = ep[j + 1], s2 = ep[j + 2], s3 = ep[j + 3];
        int s4 = ep[j + 4], s5 = ep[j + 5], s6 = ep[j + 6], s7 = ep[j + 7];
        float4 v0 = *(const float4*)&g_h[s0 * OUT_C + g * 4];
        float4 v1 = *(const float4*)&g_h[s1 * OUT_C + g * 4];
        float4 v2 = *(const float4*)&g_h[s2 * OUT_C + g * 4];
        float4 v3 = *(const float4*)&g_h[s3 * OUT_C + g * 4];
        float4 v4 = *(const float4*)&g_h[s4 * OUT_C + g * 4];
        float4 v5 = *(const float4*)&g_h[s5 * OUT_C + g * 4];
        float4 v6 = *(const float4*)&g_h[s6 * OUT_C + g * 4];
        float4 v7 = *(const float4*)&g_h[s7 * OUT_C + g * 4];
        acc.x += ((v0.x + v1.x) + (v2.x + v3.x)) + ((v4.x + v5.x) + (v6.x + v7.x));
        acc.y += ((v0.y + v1.y) + (v2.y + v3.y)) + ((v4.y + v5.y) + (v6.y + v7.y));
        acc.z += ((v0.z + v1.z) + (v2.z + v3.z)) + ((v4.z + v5.z) + (v6.z + v7.z));
        acc.w += ((v0.w + v1.w) + (v2.w + v3.w)) + ((v4.w + v5.w) + (v6.w + v7.w));
    }
    for (; j < cnt; j++) {
        int s = ep[j];
        float4 v = *(const float4*)&g_h[s * OUT_C + g * 4];
        acc.x += v.x; acc.y += v.y; acc.z += v.z; acc.w += v.w;
    }

    float rn = rsqrtf(fmaxf((float)cnt, 1.0f));
    float4 b = bias4[g];
    float4 r;
    r.x = acc.x * rn + b.x;
    r.y = acc.y * rn + b.y;
    r.z = acc.z * rn + b.z;
    r.w = acc.w * rn + b.w;
    __stcs((float4*)&out[node * OUT_C + g * 4], r);
}

// ---------------------------------------------------------------------------
extern "C" void kernel_launch(void* const* d_in, const int* in_sizes, int n_in,
                              void* d_out, int out_size) {
    const float* x      = (const float*)d_in[0];
    const float* weight = (const float*)d_in[1];
    const float* bias   = (const float*)d_in[2];
    const int*   src    = (const int*)d_in[3];
    const int*   dst    = (const int*)d_in[4];
    float* out = (float*)d_out;

    // zero degree counters via memset node (DMA)
    void* degs_ptr = nullptr;
    cudaGetSymbolAddress(&degs_ptr, g_degs);
    cudaMemsetAsync(degs_ptr, 0, 2 * N_NODES * sizeof(int));

    degree_kernel<<<(N_EDGES / 4 + 255) / 256, 256>>>((const int4*)src, (const int4*)dst);

    // CSR offsets (exclusive scan of deg_in)
    scan_block_kernel<<<N_SCAN_BLOCKS, SCAN_BLOCK>>>();
    add_offsets_kernel<<<N_SCAN_BLOCKS, SCAN_BLOCK>>>();

    // h = (x * norm_src) @ W   (needs deg_out only)
    gemm_kernel<<<(N_NODES + 127) / 128, 256>>>(x, weight);

    // group edges by dst (row_start becomes row end)
    csr_fill_kernel<<<(N_EDGES / 4 + 255) / 256, 256>>>((const int4*)src, (const int4*)dst);

    // pull aggregation + norm_dst + bias, single write
    int nwarps = (N_NODES + 1) / 2;
    aggregate_kernel<<<(nwarps + 7) / 8, 256>>>((const float4*)bias, out);
}

// round 6
// speedup vs baseline: 1.4648x; 1.4648x over previous
#include <cuda_runtime.h>

#define N_NODES 100000
#define N_EDGES 1600000
#define IN_C 128
#define OUT_C 64

#define SCAN_BLOCK 1024
#define N_SCAN_BLOCKS ((N_NODES + SCAN_BLOCK - 1) / SCAN_BLOCK)   // 98

// ------------------------- device scratch (no alloc allowed) ----------------
__device__ float g_h[N_NODES * OUT_C];     // 25.6 MB (L2-resident)
__device__ int   g_degs[2 * N_NODES];      // [0,N): deg_out   [N,2N): deg_in
__device__ int   g_row_start[N_NODES];     // excl scan of deg_in; after fill = row END
__device__ int   g_esrc[N_EDGES];          // src indices grouped by dst
__device__ int   g_bsum[N_SCAN_BLOCKS];

// ---------------------------------------------------------------------------
// 1) degree counting — int4-vectorized, streaming index reads
// ---------------------------------------------------------------------------
__global__ __launch_bounds__(256) void degree_kernel(const int4* __restrict__ src4,
                                                     const int4* __restrict__ dst4) {
    int i = blockIdx.x * blockDim.x + threadIdx.x;
    if (i < N_EDGES / 4) {
        int4 s = __ldcs(&src4[i]);
        int4 d = __ldcs(&dst4[i]);
        atomicAdd(&g_degs[s.x], 1);
        atomicAdd(&g_degs[s.y], 1);
        atomicAdd(&g_degs[s.z], 1);
        atomicAdd(&g_degs[s.w], 1);
        atomicAdd(&g_degs[N_NODES + d.x], 1);
        atomicAdd(&g_degs[N_NODES + d.y], 1);
        atomicAdd(&g_degs[N_NODES + d.z], 1);
        atomicAdd(&g_degs[N_NODES + d.w], 1);
    }
}

// ---------------------------------------------------------------------------
// 2) block-level scan of deg_in -> chunk-local exclusive prefix + block totals
// ---------------------------------------------------------------------------
__global__ __launch_bounds__(SCAN_BLOCK) void scan_block_kernel() {
    __shared__ int sh[SCAN_BLOCK];
    int t = threadIdx.x;
    int i = blockIdx.x * SCAN_BLOCK + t;
    int v = (i < N_NODES) ? g_degs[N_NODES + i] : 0;
    sh[t] = v;
    __syncthreads();
    #pragma unroll
    for (int off = 1; off < SCAN_BLOCK; off <<= 1) {
        int add = (t >= off) ? sh[t - off] : 0;
        __syncthreads();
        sh[t] += add;
        __syncthreads();
    }
    if (i < N_NODES) g_row_start[i] = sh[t] - v;   // exclusive (chunk-local)
    if (t == SCAN_BLOCK - 1) g_bsum[blockIdx.x] = sh[t];
}

// ---------------------------------------------------------------------------
// 3) every block scans the 98 block-sums in smem and adds its offset.
// ---------------------------------------------------------------------------
__global__ __launch_bounds__(SCAN_BLOCK) void add_offsets_kernel() {
    __shared__ int sh[128];
    int t = threadIdx.x;
    if (t < 128) sh[t] = (t < N_SCAN_BLOCKS) ? g_bsum[t] : 0;
    __syncthreads();
    #pragma unroll
    for (int off = 1; off < 128; off <<= 1) {
        int add = (t < 128 && t >= off) ? sh[t - off] : 0;
        __syncthreads();
        if (t < 128) sh[t] += add;
        __syncthreads();
    }
    int i = blockIdx.x * SCAN_BLOCK + t;
    if (i < N_NODES) {
        int excl = sh[blockIdx.x] - g_bsum[blockIdx.x];  // inclusive - own = exclusive
        g_row_start[i] += excl;
    }
}

// ---------------------------------------------------------------------------
// 4) CSR fill: group src indices by dst.  g_row_start doubles as the cursor;
//    after this kernel g_row_start[d] == row END of d.
// ---------------------------------------------------------------------------
__global__ __launch_bounds__(256) void csr_fill_kernel(const int4* __restrict__ src4,
                                                       const int4* __restrict__ dst4) {
    int i = blockIdx.x * blockDim.x + threadIdx.x;
    if (i < N_EDGES / 4) {
        int4 s = __ldcs(&src4[i]);
        int4 d = __ldcs(&dst4[i]);
        g_esrc[atomicAdd(&g_row_start[d.x], 1)] = s.x;
        g_esrc[atomicAdd(&g_row_start[d.y], 1)] = s.y;
        g_esrc[atomicAdd(&g_row_start[d.z], 1)] = s.z;
        g_esrc[atomicAdd(&g_row_start[d.w], 1)] = s.w;
    }
}

// ---------------------------------------------------------------------------
// 5) GEMM: h = (x * norm_src) @ W  — register-tiled outer product, f32x2.
//    Block: 256 nodes x 64 cols. Thread: 8 nodes x 8 cols (32 f32x2 accs).
//    Per k-step a thread reads 8 x + 8 w floats from smem for 64 MACs.
// ---------------------------------------------------------------------------
__global__ __launch_bounds__(256, 2) void gemm_kernel(const float* __restrict__ x,
                                                      const float* __restrict__ w) {
    __shared__ __align__(16) float xs[32][256];   // 32 KB : k-chunk of x, transposed
    __shared__ __align__(16) float ws[32][64];    //  8 KB : k-chunk of W

    const int t = threadIdx.x;
    const int lane = t & 31;
    const int wid = t >> 5;                 // col group 0..7 (8 cols)
    const int nbase = blockIdx.x * 256;

    unsigned long long acc[8][4];
    #pragma unroll
    for (int i = 0; i < 8; i++)
        #pragma unroll
        for (int j = 0; j < 4; j++) acc[i][j] = 0ULL;

    for (int kc = 0; kc < 4; kc++) {
        __syncthreads();
        // stage W chunk [32][64] = 512 float4s : TWO float4s per thread
        #pragma unroll
        for (int j = 0; j < 2; j++) {
            int idx = t + 256 * j;           // 0..511
            int row = idx >> 4;              // 0..31
            int c4  = idx & 15;              // 0..15
            float4 wv = *(const float4*)&w[(kc * 32 + row) * OUT_C + c4 * 4];
            *(float4*)&ws[row][c4 * 4] = wv;
        }
        // stage x chunk: thread t owns node nbase+t, ks [kc*32, +32), transposed write
        {
            int nd = nbase + t;
            float4 v[8];
            if (nd < N_NODES) {
                const float4* xp = (const float4*)&x[nd * IN_C + kc * 32];
                #pragma unroll
                for (int q = 0; q < 8; q++) v[q] = __ldcs(xp + q);
            } else {
                #pragma unroll
                for (int q = 0; q < 8; q++) v[q] = make_float4(0.f, 0.f, 0.f, 0.f);
            }
            #pragma unroll
            for (int q = 0; q < 8; q++) {
                xs[4 * q + 0][t] = v[q].x;
                xs[4 * q + 1][t] = v[q].y;
                xs[4 * q + 2][t] = v[q].z;
                xs[4 * q + 3][t] = v[q].w;
            }
        }
        __syncthreads();

        #pragma unroll
        for (int kk = 0; kk < 32; kk++) {
            float4 a0 = *(const float4*)&xs[kk][lane * 4];          // nodes lane*4..+3
            float4 a1 = *(const float4*)&xs[kk][128 + lane * 4];    // nodes 128+lane*4..+3
            float4 w0 = *(const float4*)&ws[kk][wid * 8];           // cols wid*8..+3
            float4 w1 = *(const float4*)&ws[kk][wid * 8 + 4];

            unsigned long long wp[4], ap[8];
            asm("mov.b64 %0, {%1, %2};" : "=l"(wp[0]) : "r"(__float_as_uint(w0.x)), "r"(__float_as_uint(w0.y)));
            asm("mov.b64 %0, {%1, %2};" : "=l"(wp[1]) : "r"(__float_as_uint(w0.z)), "r"(__float_as_uint(w0.w)));
            asm("mov.b64 %0, {%1, %2};" : "=l"(wp[2]) : "r"(__float_as_uint(w1.x)), "r"(__float_as_uint(w1.y)));
            asm("mov.b64 %0, {%1, %2};" : "=l"(wp[3]) : "r"(__float_as_uint(w1.z)), "r"(__float_as_uint(w1.w)));
            asm("mov.b64 %0, {%1, %1};" : "=l"(ap[0]) : "r"(__float_as_uint(a0.x)));
            asm("mov.b64 %0, {%1, %1};" : "=l"(ap[1]) : "r"(__float_as_uint(a0.y)));
            asm("mov.b64 %0, {%1, %1};" : "=l"(ap[2]) : "r"(__float_as_uint(a0.z)));
            asm("mov.b64 %0, {%1, %1};" : "=l"(ap[3]) : "r"(__float_as_uint(a0.w)));
            asm("mov.b64 %0, {%1, %1};" : "=l"(ap[4]) : "r"(__float_as_uint(a1.x)));
            asm("mov.b64 %0, {%1, %1};" : "=l"(ap[5]) : "r"(__float_as_uint(a1.y)));
            asm("mov.b64 %0, {%1, %1};" : "=l"(ap[6]) : "r"(__float_as_uint(a1.z)));
            asm("mov.b64 %0, {%1, %1};" : "=l"(ap[7]) : "r"(__float_as_uint(a1.w)));

            #pragma unroll
            for (int i = 0; i < 8; i++)
                #pragma unroll
                for (int j = 0; j < 4; j++)
                    asm("fma.rn.f32x2 %0, %1, %2, %0;" : "+l"(acc[i][j]) : "l"(ap[i]), "l"(wp[j]));
        }
    }

    // epilogue: apply norm_src, store 8 cols per node
    #pragma unroll
    for (int i = 0; i < 8; i++) {
        int node = nbase + ((i < 4) ? (lane * 4 + i) : (128 + lane * 4 + (i - 4)));
        if (node < N_NODES) {
            float rn = rsqrtf(fmaxf((float)g_degs[node], 1.0f));
            float o[8];
            #pragma unroll
            for (int j = 0; j < 4; j++) {
                unsigned int lo, hi;
                asm("mov.b64 {%0, %1}, %2;" : "=r"(lo), "=r"(hi) : "l"(acc[i][j]));
                o[2 * j]     = __uint_as_float(lo) * rn;
                o[2 * j + 1] = __uint_as_float(hi) * rn;
            }
            float* hp = &g_h[node * OUT_C + wid * 8];
            *(float4*)&hp[0] = make_float4(o[0], o[1], o[2], o[3]);
            *(float4*)&hp[4] = make_float4(o[4], o[5], o[6], o[7]);
        }
    }
}

// ---------------------------------------------------------------------------
// 6) pull aggregation: out[n] = norm_dst[n] * sum h[src_e] + bias
// ---------------------------------------------------------------------------
__global__ __launch_bounds__(256) void aggregate_kernel(const float4* __restrict__ bias4,
                                                        float* __restrict__ out) {
    int gwarp = (blockIdx.x * 256 + threadIdx.x) >> 5;
    int lane  = threadIdx.x & 31;
    int node  = gwarp * 2 + (lane >> 4);
    if (node >= N_NODES) return;
    int g = lane & 15;

    int cnt = g_degs[N_NODES + node];
    int start = g_row_start[node] - cnt;     // row_start was bumped to END by fill
    const int* ep = &g_esrc[start];

    float4 acc = make_float4(0.f, 0.f, 0.f, 0.f);
    int j = 0;
    for (; j + 8 <= cnt; j += 8) {
        int s0 = ep[j],     s1 = ep[j + 1], s2 = ep[j + 2], s3 = ep[j + 3];
        int s4 = ep[j + 4], s5 = ep[j + 5], s6 = ep[j + 6], s7 = ep[j + 7];
        float4 v0 = *(const float4*)&g_h[s0 * OUT_C + g * 4];
        float4 v1 = *(const float4*)&g_h[s1 * OUT_C + g * 4];
        float4 v2 = *(const float4*)&g_h[s2 * OUT_C + g * 4];
        float4 v3 = *(const float4*)&g_h[s3 * OUT_C + g * 4];
        float4 v4 = *(const float4*)&g_h[s4 * OUT_C + g * 4];
        float4 v5 = *(const float4*)&g_h[s5 * OUT_C + g * 4];
        float4 v6 = *(const float4*)&g_h[s6 * OUT_C + g * 4];
        float4 v7 = *(const float4*)&g_h[s7 * OUT_C + g * 4];
        acc.x += ((v0.x + v1.x) + (v2.x + v3.x)) + ((v4.x + v5.x) + (v6.x + v7.x));
        acc.y += ((v0.y + v1.y) + (v2.y + v3.y)) + ((v4.y + v5.y) + (v6.y + v7.y));
        acc.z += ((v0.z + v1.z) + (v2.z + v3.z)) + ((v4.z + v5.z) + (v6.z + v7.z));
        acc.w += ((v0.w + v1.w) + (v2.w + v3.w)) + ((v4.w + v5.w) + (v6.w + v7.w));
    }
    for (; j < cnt; j++) {
        int s = ep[j];
        float4 v = *(const float4*)&g_h[s * OUT_C + g * 4];
        acc.x += v.x; acc.y += v.y; acc.z += v.z; acc.w += v.w;
    }

    float rn = rsqrtf(fmaxf((float)cnt, 1.0f));
    float4 b = bias4[g];
    float4 r;
    r.x = acc.x * rn + b.x;
    r.y = acc.y * rn + b.y;
    r.z = acc.z * rn + b.z;
    r.w = acc.w * rn + b.w;
    __stcs((float4*)&out[node * OUT_C + g * 4], r);
}

// ---------------------------------------------------------------------------
extern "C" void kernel_launch(void* const* d_in, const int* in_sizes, int n_in,
                              void* d_out, int out_size) {
    const float* x      = (const float*)d_in[0];
    const float* weight = (const float*)d_in[1];
    const float* bias   = (const float*)d_in[2];
    const int*   src    = (const int*)d_in[3];
    const int*   dst    = (const int*)d_in[4];
    float* out = (float*)d_out;

    // zero degree counters via memset node (DMA)
    void* degs_ptr = nullptr;
    cudaGetSymbolAddress(&degs_ptr, g_degs);
    cudaMemsetAsync(degs_ptr, 0, 2 * N_NODES * sizeof(int));

    degree_kernel<<<(N_EDGES / 4 + 255) / 256, 256>>>((const int4*)src, (const int4*)dst);

    // CSR offsets (exclusive scan of deg_in)
    scan_block_kernel<<<N_SCAN_BLOCKS, SCAN_BLOCK>>>();
    add_offsets_kernel<<<N_SCAN_BLOCKS, SCAN_BLOCK>>>();

    // h = (x * norm_src) @ W   (needs deg_out only)
    gemm_kernel<<<(N_NODES + 255) / 256, 256>>>(x, weight);

    // group edges by dst (row_start becomes row end)
    csr_fill_kernel<<<(N_EDGES / 4 + 255) / 256, 256>>>((const int4*)src, (const int4*)dst);

    // pull aggregation + norm_dst + bias, single write
    int nwarps = (N_NODES + 1) / 2;
    aggregate_kernel<<<(nwarps + 7) / 8, 256>>>((const float4*)bias, out);
}

// round 7
// speedup vs baseline: 1.5053x; 1.0276x over previous
#include <cuda_runtime.h>
#include <cuda_fp16.h>

#define N_NODES 100000
#define N_EDGES 1600000
#define IN_C 128
#define OUT_C 64

#define SCAN_BLOCK 1024
#define N_SCAN_BLOCKS ((N_NODES + SCAN_BLOCK - 1) / SCAN_BLOCK)   // 98

// ------------------------- device scratch (no alloc allowed) ----------------
__device__ __half g_h16[N_NODES * OUT_C];  // 12.8 MB (L2-resident)
__device__ int    g_degs[2 * N_NODES];     // [0,N): deg_out   [N,2N): deg_in
__device__ int    g_row_start[N_NODES];    // excl scan of deg_in; after fill = row END
__device__ int    g_esrc[N_EDGES];         // src indices grouped by dst
__device__ int    g_bsum[N_SCAN_BLOCKS];

// ---------------------------------------------------------------------------
// 1) degree counting — int4-vectorized, streaming index reads
// ---------------------------------------------------------------------------
__global__ __launch_bounds__(256) void degree_kernel(const int4* __restrict__ src4,
                                                     const int4* __restrict__ dst4) {
    int i = blockIdx.x * blockDim.x + threadIdx.x;
    if (i < N_EDGES / 4) {
        int4 s = __ldcs(&src4[i]);
        int4 d = __ldcs(&dst4[i]);
        atomicAdd(&g_degs[s.x], 1);
        atomicAdd(&g_degs[s.y], 1);
        atomicAdd(&g_degs[s.z], 1);
        atomicAdd(&g_degs[s.w], 1);
        atomicAdd(&g_degs[N_NODES + d.x], 1);
        atomicAdd(&g_degs[N_NODES + d.y], 1);
        atomicAdd(&g_degs[N_NODES + d.z], 1);
        atomicAdd(&g_degs[N_NODES + d.w], 1);
    }
}

// ---------------------------------------------------------------------------
// 2) block-level scan of deg_in -> chunk-local exclusive prefix + block totals
// ---------------------------------------------------------------------------
__global__ __launch_bounds__(SCAN_BLOCK) void scan_block_kernel() {
    __shared__ int sh[SCAN_BLOCK];
    int t = threadIdx.x;
    int i = blockIdx.x * SCAN_BLOCK + t;
    int v = (i < N_NODES) ? g_degs[N_NODES + i] : 0;
    sh[t] = v;
    __syncthreads();
    #pragma unroll
    for (int off = 1; off < SCAN_BLOCK; off <<= 1) {
        int add = (t >= off) ? sh[t - off] : 0;
        __syncthreads();
        sh[t] += add;
        __syncthreads();
    }
    if (i < N_NODES) g_row_start[i] = sh[t] - v;   // exclusive (chunk-local)
    if (t == SCAN_BLOCK - 1) g_bsum[blockIdx.x] = sh[t];
}

// ---------------------------------------------------------------------------
// 3) every block scans the 98 block-sums in smem and adds its offset.
// ---------------------------------------------------------------------------
__global__ __launch_bounds__(SCAN_BLOCK) void add_offsets_kernel() {
    __shared__ int sh[128];
    int t = threadIdx.x;
    if (t < 128) sh[t] = (t < N_SCAN_BLOCKS) ? g_bsum[t] : 0;
    __syncthreads();
    #pragma unroll
    for (int off = 1; off < 128; off <<= 1) {
        int add = (t < 128 && t >= off) ? sh[t - off] : 0;
        __syncthreads();
        if (t < 128) sh[t] += add;
        __syncthreads();
    }
    int i = blockIdx.x * SCAN_BLOCK + t;
    if (i < N_NODES) {
        int excl = sh[blockIdx.x] - g_bsum[blockIdx.x];  // inclusive - own = exclusive
        g_row_start[i] += excl;
    }
}

// ---------------------------------------------------------------------------
// 4) CSR fill: group src indices by dst.  g_row_start doubles as the cursor;
//    after this kernel g_row_start[d] == row END of d.
// ---------------------------------------------------------------------------
__global__ __launch_bounds__(256) void csr_fill_kernel(const int4* __restrict__ src4,
                                                       const int4* __restrict__ dst4) {
    int i = blockIdx.x * blockDim.x + threadIdx.x;
    if (i < N_EDGES / 4) {
        int4 s = __ldcs(&src4[i]);
        int4 d = __ldcs(&dst4[i]);
        g_esrc[atomicAdd(&g_row_start[d.x], 1)] = s.x;
        g_esrc[atomicAdd(&g_row_start[d.y], 1)] = s.y;
        g_esrc[atomicAdd(&g_row_start[d.z], 1)] = s.z;
        g_esrc[atomicAdd(&g_row_start[d.w], 1)] = s.w;
    }
}

// ---------------------------------------------------------------------------
// 5) GEMM: h = (x * norm_src) @ W  — mov-free f32x2 outer product.
//    acc[i][j] = f32x2 over ADJACENT NODE PAIR i (4 pairs = 8 nodes), col j.
//    a-operands come straight out of LDS.128 (two node-pairs per load);
//    w-operands are pre-duplicated {w,w} pairs in smem (broadcast LDS.128).
//    Inner loop per k: 6 LDS + 32 FFMA2, zero movs.
// ---------------------------------------------------------------------------
__global__ __launch_bounds__(256, 2) void gemm_kernel(const float* __restrict__ x,
                                                      const float* __restrict__ w) {
    __shared__ __align__(16) float xs[32][256];              // 32 KB
    __shared__ __align__(16) unsigned long long ws2[32][64]; // 16 KB ({w,w} pairs)

    const int t = threadIdx.x;
    const int lane = t & 31;
    const int wid = t >> 5;                 // col group 0..7 (8 cols)
    const int nbase = blockIdx.x * 256;

    unsigned long long acc[4][8];
    #pragma unroll
    for (int i = 0; i < 4; i++)
        #pragma unroll
        for (int j = 0; j < 8; j++) acc[i][j] = 0ULL;

    for (int kc = 0; kc < 4; kc++) {
        __syncthreads();
        // stage W chunk [32][64] pre-duplicated: 512 source float4s, 2/thread
        #pragma unroll
        for (int j = 0; j < 2; j++) {
            int idx = t + 256 * j;           // 0..511
            int row = idx >> 4;              // 0..31
            int c4  = idx & 15;              // 0..15
            float4 wv = *(const float4*)&w[(kc * 32 + row) * OUT_C + c4 * 4];
            ulonglong2 p0, p1;
            asm("mov.b64 %0, {%1, %1};" : "=l"(p0.x) : "r"(__float_as_uint(wv.x)));
            asm("mov.b64 %0, {%1, %1};" : "=l"(p0.y) : "r"(__float_as_uint(wv.y)));
            asm("mov.b64 %0, {%1, %1};" : "=l"(p1.x) : "r"(__float_as_uint(wv.z)));
            asm("mov.b64 %0, {%1, %1};" : "=l"(p1.y) : "r"(__float_as_uint(wv.w)));
            *(ulonglong2*)&ws2[row][c4 * 4]     = p0;
            *(ulonglong2*)&ws2[row][c4 * 4 + 2] = p1;
        }
        // stage x chunk: thread t owns node nbase+t, ks [kc*32,+32), transposed
        {
            int nd = nbase + t;
            float4 v[8];
            if (nd < N_NODES) {
                const float4* xp = (const float4*)&x[nd * IN_C + kc * 32];
                #pragma unroll
                for (int q = 0; q < 8; q++) v[q] = __ldcs(xp + q);
            } else {
                #pragma unroll
                for (int q = 0; q < 8; q++) v[q] = make_float4(0.f, 0.f, 0.f, 0.f);
            }
            #pragma unroll
            for (int q = 0; q < 8; q++) {
                xs[4 * q + 0][t] = v[q].x;
                xs[4 * q + 1][t] = v[q].y;
                xs[4 * q + 2][t] = v[q].z;
                xs[4 * q + 3][t] = v[q].w;
            }
        }
        __syncthreads();

        #pragma unroll
        for (int kk = 0; kk < 32; kk++) {
            // node pairs, straight from LDS.128 (no packing needed)
            ulonglong2 a01 = *(const ulonglong2*)&xs[kk][lane * 4];        // {n0,n1},{n2,n3}
            ulonglong2 a23 = *(const ulonglong2*)&xs[kk][128 + lane * 4];  // {n128..}
            // duplicated w pairs, broadcast LDS.128
            ulonglong2 w01 = *(const ulonglong2*)&ws2[kk][wid * 8];
            ulonglong2 w23 = *(const ulonglong2*)&ws2[kk][wid * 8 + 2];
            ulonglong2 w45 = *(const ulonglong2*)&ws2[kk][wid * 8 + 4];
            ulonglong2 w67 = *(const ulonglong2*)&ws2[kk][wid * 8 + 6];
            unsigned long long ap[4] = {a01.x, a01.y, a23.x, a23.y};
            unsigned long long wp[8] = {w01.x, w01.y, w23.x, w23.y,
                                        w45.x, w45.y, w67.x, w67.y};
            #pragma unroll
            for (int i = 0; i < 4; i++)
                #pragma unroll
                for (int j = 0; j < 8; j++)
                    asm("fma.rn.f32x2 %0, %1, %2, %0;" : "+l"(acc[i][j]) : "l"(ap[i]), "l"(wp[j]));
        }
    }

    // epilogue: unpack pairs, apply norm_src, store fp16 (8 cols per node)
    #pragma unroll
    for (int i = 0; i < 4; i++) {
        int nA = nbase + ((i < 2) ? (lane * 4 + 2 * i) : (128 + lane * 4 + 2 * (i - 2)));
        int nB = nA + 1;
        float lo[8], hi[8];
        #pragma unroll
        for (int j = 0; j < 8; j++) {
            unsigned int l, h;
            asm("mov.b64 {%0, %1}, %2;" : "=r"(l), "=r"(h) : "l"(acc[i][j]));
            lo[j] = __uint_as_float(l);
            hi[j] = __uint_as_float(h);
        }
        if (nA < N_NODES) {
            float rn = rsqrtf(fmaxf((float)g_degs[nA], 1.0f));
            uint4 u;
            __half2 h0 = __floats2half2_rn(lo[0] * rn, lo[1] * rn);
            __half2 h1 = __floats2half2_rn(lo[2] * rn, lo[3] * rn);
            __half2 h2 = __floats2half2_rn(lo[4] * rn, lo[5] * rn);
            __half2 h3 = __floats2half2_rn(lo[6] * rn, lo[7] * rn);
            u.x = *(unsigned*)&h0; u.y = *(unsigned*)&h1;
            u.z = *(unsigned*)&h2; u.w = *(unsigned*)&h3;
            *(uint4*)&g_h16[nA * OUT_C + wid * 8] = u;
        }
        if (nB < N_NODES) {
            float rn = rsqrtf(fmaxf((float)g_degs[nB], 1.0f));
            uint4 u;
            __half2 h0 = __floats2half2_rn(hi[0] * rn, hi[1] * rn);
            __half2 h1 = __floats2half2_rn(hi[2] * rn, hi[3] * rn);
            __half2 h2 = __floats2half2_rn(hi[4] * rn, hi[5] * rn);
            __half2 h3 = __floats2half2_rn(hi[6] * rn, hi[7] * rn);
            u.x = *(unsigned*)&h0; u.y = *(unsigned*)&h1;
            u.z = *(unsigned*)&h2; u.w = *(unsigned*)&h3;
            *(uint4*)&g_h16[nB * OUT_C + wid * 8] = u;
        }
    }
}

// ---------------------------------------------------------------------------
// 6) pull aggregation (fp16 gather, fp32 accumulate):
//    out[n] = norm_dst[n] * sum h[src_e] + bias
//    16 threads/node (4 fp16 cols = 8B each), 2 nodes/warp, 8-deep unroll.
// ---------------------------------------------------------------------------
__global__ __launch_bounds__(256) void aggregate_kernel(const float4* __restrict__ bias4,
                                                        float* __restrict__ out) {
    int gwarp = (blockIdx.x * 256 + threadIdx.x) >> 5;
    int lane  = threadIdx.x & 31;
    int node  = gwarp * 2 + (lane >> 4);
    if (node >= N_NODES) return;
    int g = lane & 15;

    int cnt = g_degs[N_NODES + node];
    int start = g_row_start[node] - cnt;     // row_start was bumped to END by fill
    const int* ep = &g_esrc[start];

    float4 acc = make_float4(0.f, 0.f, 0.f, 0.f);
    int j = 0;
    for (; j + 8 <= cnt; j += 8) {
        uint2 r[8];
        #pragma unroll
        for (int q = 0; q < 8; q++) {
            int s = ep[j + q];
            r[q] = *(const uint2*)&g_h16[s * OUT_C + g * 4];
        }
        #pragma unroll
        for (int q = 0; q < 8; q++) {
            float2 f0 = __half22float2(*(__half2*)&r[q].x);
            float2 f1 = __half22float2(*(__half2*)&r[q].y);
            acc.x += f0.x; acc.y += f0.y; acc.z += f1.x; acc.w += f1.y;
        }
    }
    for (; j < cnt; j++) {
        int s = ep[j];
        uint2 r = *(const uint2*)&g_h16[s * OUT_C + g * 4];
        float2 f0 = __half22float2(*(__half2*)&r.x);
        float2 f1 = __half22float2(*(__half2*)&r.y);
        acc.x += f0.x; acc.y += f0.y; acc.z += f1.x; acc.w += f1.y;
    }

    float rn = rsqrtf(fmaxf((float)cnt, 1.0f));
    float4 b = bias4[g];
    float4 r;
    r.x = acc.x * rn + b.x;
    r.y = acc.y * rn + b.y;
    r.z = acc.z * rn + b.z;
    r.w = acc.w * rn + b.w;
    __stcs((float4*)&out[node * OUT_C + g * 4], r);
}

// ---------------------------------------------------------------------------
extern "C" void kernel_launch(void* const* d_in, const int* in_sizes, int n_in,
                              void* d_out, int out_size) {
    const float* x      = (const float*)d_in[0];
    const float* weight = (const float*)d_in[1];
    const float* bias   = (const float*)d_in[2];
    const int*   src    = (const int*)d_in[3];
    const int*   dst    = (const int*)d_in[4];
    float* out = (float*)d_out;

    // zero degree counters via memset node (DMA)
    void* degs_ptr = nullptr;
    cudaGetSymbolAddress(&degs_ptr, g_degs);
    cudaMemsetAsync(degs_ptr, 0, 2 * N_NODES * sizeof(int));

    degree_kernel<<<(N_EDGES / 4 + 255) / 256, 256>>>((const int4*)src, (const int4*)dst);

    // CSR offsets (exclusive scan of deg_in)
    scan_block_kernel<<<N_SCAN_BLOCKS, SCAN_BLOCK>>>();
    add_offsets_kernel<<<N_SCAN_BLOCKS, SCAN_BLOCK>>>();

    // h = (x * norm_src) @ W   (needs deg_out only)
    gemm_kernel<<<(N_NODES + 255) / 256, 256>>>(x, weight);

    // group edges by dst (row_start becomes row end)
    csr_fill_kernel<<<(N_EDGES / 4 + 255) / 256, 256>>>((const int4*)src, (const int4*)dst);

    // pull aggregation + norm_dst + bias, single write
    int nwarps = (N_NODES + 1) / 2;
    aggregate_kernel<<<(nwarps + 7) / 8, 256>>>((const float4*)bias, out);
}

// round 8
// speedup vs baseline: 1.7540x; 1.1652x over previous
#include <cuda_runtime.h>
#include <cuda_fp16.h>

#define N_NODES 100000
#define N_EDGES 1600000
#define IN_C 128
#define OUT_C 64

#define SCAN_BLOCK 1024
#define N_SCAN_BLOCKS ((N_NODES + SCAN_BLOCK - 1) / SCAN_BLOCK)   // 98

// ------------------------- device scratch (no alloc allowed) ----------------
__device__ __half g_h16[N_NODES * OUT_C];  // 12.8 MB (L2-resident)
__device__ int    g_degs[2 * N_NODES];     // [0,N): deg_out   [N,2N): deg_in
__device__ int    g_row_start[N_NODES];    // excl scan of deg_in; after fill = row END
__device__ int    g_esrc[N_EDGES];         // src indices grouped by dst
__device__ int    g_bsum[N_SCAN_BLOCKS];

// ---------------------------------------------------------------------------
// 1) degree counting — int4-vectorized, streaming index reads
// ---------------------------------------------------------------------------
__global__ __launch_bounds__(256) void degree_kernel(const int4* __restrict__ src4,
                                                     const int4* __restrict__ dst4) {
    int i = blockIdx.x * blockDim.x + threadIdx.x;
    if (i < N_EDGES / 4) {
        int4 s = __ldcs(&src4[i]);
        int4 d = __ldcs(&dst4[i]);
        atomicAdd(&g_degs[s.x], 1);
        atomicAdd(&g_degs[s.y], 1);
        atomicAdd(&g_degs[s.z], 1);
        atomicAdd(&g_degs[s.w], 1);
        atomicAdd(&g_degs[N_NODES + d.x], 1);
        atomicAdd(&g_degs[N_NODES + d.y], 1);
        atomicAdd(&g_degs[N_NODES + d.z], 1);
        atomicAdd(&g_degs[N_NODES + d.w], 1);
    }
}

// ---------------------------------------------------------------------------
// 2) block-level scan of deg_in -> chunk-local exclusive prefix + block totals
// ---------------------------------------------------------------------------
__global__ __launch_bounds__(SCAN_BLOCK) void scan_block_kernel() {
    __shared__ int sh[SCAN_BLOCK];
    int t = threadIdx.x;
    int i = blockIdx.x * SCAN_BLOCK + t;
    int v = (i < N_NODES) ? g_degs[N_NODES + i] : 0;
    sh[t] = v;
    __syncthreads();
    #pragma unroll
    for (int off = 1; off < SCAN_BLOCK; off <<= 1) {
        int add = (t >= off) ? sh[t - off] : 0;
        __syncthreads();
        sh[t] += add;
        __syncthreads();
    }
    if (i < N_NODES) g_row_start[i] = sh[t] - v;   // exclusive (chunk-local)
    if (t == SCAN_BLOCK - 1) g_bsum[blockIdx.x] = sh[t];
}

// ---------------------------------------------------------------------------
// 3) every block scans the 98 block-sums in smem and adds its offset.
// ---------------------------------------------------------------------------
__global__ __launch_bounds__(SCAN_BLOCK) void add_offsets_kernel() {
    __shared__ int sh[128];
    int t = threadIdx.x;
    if (t < 128) sh[t] = (t < N_SCAN_BLOCKS) ? g_bsum[t] : 0;
    __syncthreads();
    #pragma unroll
    for (int off = 1; off < 128; off <<= 1) {
        int add = (t < 128 && t >= off) ? sh[t - off] : 0;
        __syncthreads();
        if (t < 128) sh[t] += add;
        __syncthreads();
    }
    int i = blockIdx.x * SCAN_BLOCK + t;
    if (i < N_NODES) {
        int excl = sh[blockIdx.x] - g_bsum[blockIdx.x];  // inclusive - own = exclusive
        g_row_start[i] += excl;
    }
}

// ---------------------------------------------------------------------------
// 4) CSR fill: group src indices by dst.  g_row_start doubles as the cursor;
//    after this kernel g_row_start[d] == row END of d.
// ---------------------------------------------------------------------------
__global__ __launch_bounds__(256) void csr_fill_kernel(const int4* __restrict__ src4,
                                                       const int4* __restrict__ dst4) {
    int i = blockIdx.x * blockDim.x + threadIdx.x;
    if (i < N_EDGES / 4) {
        int4 s = __ldcs(&src4[i]);
        int4 d = __ldcs(&dst4[i]);
        g_esrc[atomicAdd(&g_row_start[d.x], 1)] = s.x;
        g_esrc[atomicAdd(&g_row_start[d.y], 1)] = s.y;
        g_esrc[atomicAdd(&g_row_start[d.z], 1)] = s.z;
        g_esrc[atomicAdd(&g_row_start[d.w], 1)] = s.w;
    }
}

// ---------------------------------------------------------------------------
// 5) GEMM: h = (x * norm_src) @ W  — mov-free f32x2 outer product +
//    prefetch.global.L1 of next k-chunk (hides staging LDG latency, 0 regs).
// ---------------------------------------------------------------------------
__global__ __launch_bounds__(256, 2) void gemm_kernel(const float* __restrict__ x,
                                                      const float* __restrict__ w) {
    __shared__ __align__(16) float xs[32][256];              // 32 KB
    __shared__ __align__(16) unsigned long long ws2[32][64]; // 16 KB ({w,w} pairs)

    const int t = threadIdx.x;
    const int lane = t & 31;
    const int wid = t >> 5;                 // col group 0..7 (8 cols)
    const int nbase = blockIdx.x * 256;

    unsigned long long acc[4][8];
    #pragma unroll
    for (int i = 0; i < 4; i++)
        #pragma unroll
        for (int j = 0; j < 8; j++) acc[i][j] = 0ULL;

    // prefetch chunk 0
    {
        int nd = nbase + t;
        if (nd < N_NODES)
            asm volatile("prefetch.global.L1 [%0];" :: "l"(&x[nd * IN_C]));
        if (t < 64)
            asm volatile("prefetch.global.L1 [%0];" :: "l"(&w[t * 32]));
    }

    for (int kc = 0; kc < 4; kc++) {
        __syncthreads();
        // stage W chunk [32][64] pre-duplicated: 512 source float4s, 2/thread
        #pragma unroll
        for (int j = 0; j < 2; j++) {
            int idx = t + 256 * j;           // 0..511
            int row = idx >> 4;              // 0..31
            int c4  = idx & 15;              // 0..15
            float4 wv = *(const float4*)&w[(kc * 32 + row) * OUT_C + c4 * 4];
            ulonglong2 p0, p1;
            asm("mov.b64 %0, {%1, %1};" : "=l"(p0.x) : "r"(__float_as_uint(wv.x)));
            asm("mov.b64 %0, {%1, %1};" : "=l"(p0.y) : "r"(__float_as_uint(wv.y)));
            asm("mov.b64 %0, {%1, %1};" : "=l"(p1.x) : "r"(__float_as_uint(wv.z)));
            asm("mov.b64 %0, {%1, %1};" : "=l"(p1.y) : "r"(__float_as_uint(wv.w)));
            *(ulonglong2*)&ws2[row][c4 * 4]     = p0;
            *(ulonglong2*)&ws2[row][c4 * 4 + 2] = p1;
        }
        // stage x chunk: thread t owns node nbase+t, ks [kc*32,+32), transposed
        {
            int nd = nbase + t;
            float4 v[8];
            if (nd < N_NODES) {
                const float4* xp = (const float4*)&x[nd * IN_C + kc * 32];
                #pragma unroll
                for (int q = 0; q < 8; q++) v[q] = xp[q];
            } else {
                #pragma unroll
                for (int q = 0; q < 8; q++) v[q] = make_float4(0.f, 0.f, 0.f, 0.f);
            }
            #pragma unroll
            for (int q = 0; q < 8; q++) {
                xs[4 * q + 0][t] = v[q].x;
                xs[4 * q + 1][t] = v[q].y;
                xs[4 * q + 2][t] = v[q].z;
                xs[4 * q + 3][t] = v[q].w;
            }
        }
        __syncthreads();

        // prefetch next chunk while computing this one (L1-warm, zero regs)
        if (kc < 3) {
            int nd = nbase + t;
            if (nd < N_NODES)
                asm volatile("prefetch.global.L1 [%0];" :: "l"(&x[nd * IN_C + (kc + 1) * 32]));
            if (t < 64)
                asm volatile("prefetch.global.L1 [%0];" :: "l"(&w[(kc + 1) * 2048 + t * 32]));
        }

        #pragma unroll
        for (int kk = 0; kk < 32; kk++) {
            ulonglong2 a01 = *(const ulonglong2*)&xs[kk][lane * 4];        // {n0,n1},{n2,n3}
            ulonglong2 a23 = *(const ulonglong2*)&xs[kk][128 + lane * 4];  // {n128..}
            ulonglong2 w01 = *(const ulonglong2*)&ws2[kk][wid * 8];
            ulonglong2 w23 = *(const ulonglong2*)&ws2[kk][wid * 8 + 2];
            ulonglong2 w45 = *(const ulonglong2*)&ws2[kk][wid * 8 + 4];
            ulonglong2 w67 = *(const ulonglong2*)&ws2[kk][wid * 8 + 6];
            unsigned long long ap[4] = {a01.x, a01.y, a23.x, a23.y};
            unsigned long long wp[8] = {w01.x, w01.y, w23.x, w23.y,
                                        w45.x, w45.y, w67.x, w67.y};
            #pragma unroll
            for (int i = 0; i < 4; i++)
                #pragma unroll
                for (int j = 0; j < 8; j++)
                    asm("fma.rn.f32x2 %0, %1, %2, %0;" : "+l"(acc[i][j]) : "l"(ap[i]), "l"(wp[j]));
        }
    }

    // epilogue: unpack pairs, apply norm_src, store fp16 (8 cols per node)
    #pragma unroll
    for (int i = 0; i < 4; i++) {
        int nA = nbase + ((i < 2) ? (lane * 4 + 2 * i) : (128 + lane * 4 + 2 * (i - 2)));
        int nB = nA + 1;
        float lo[8], hi[8];
        #pragma unroll
        for (int j = 0; j < 8; j++) {
            unsigned int l, h;
            asm("mov.b64 {%0, %1}, %2;" : "=r"(l), "=r"(h) : "l"(acc[i][j]));
            lo[j] = __uint_as_float(l);
            hi[j] = __uint_as_float(h);
        }
        if (nA < N_NODES) {
            float rn = rsqrtf(fmaxf((float)g_degs[nA], 1.0f));
            uint4 u;
            __half2 h0 = __floats2half2_rn(lo[0] * rn, lo[1] * rn);
            __half2 h1 = __floats2half2_rn(lo[2] * rn, lo[3] * rn);
            __half2 h2 = __floats2half2_rn(lo[4] * rn, lo[5] * rn);
            __half2 h3 = __floats2half2_rn(lo[6] * rn, lo[7] * rn);
            u.x = *(unsigned*)&h0; u.y = *(unsigned*)&h1;
            u.z = *(unsigned*)&h2; u.w = *(unsigned*)&h3;
            *(uint4*)&g_h16[nA * OUT_C + wid * 8] = u;
        }
        if (nB < N_NODES) {
            float rn = rsqrtf(fmaxf((float)g_degs[nB], 1.0f));
            uint4 u;
            __half2 h0 = __floats2half2_rn(hi[0] * rn, hi[1] * rn);
            __half2 h1 = __floats2half2_rn(hi[2] * rn, hi[3] * rn);
            __half2 h2 = __floats2half2_rn(hi[4] * rn, hi[5] * rn);
            __half2 h3 = __floats2half2_rn(hi[6] * rn, hi[7] * rn);
            u.x = *(unsigned*)&h0; u.y = *(unsigned*)&h1;
            u.z = *(unsigned*)&h2; u.w = *(unsigned*)&h3;
            *(uint4*)&g_h16[nB * OUT_C + wid * 8] = u;
        }
    }
}

// ---------------------------------------------------------------------------
// 6) pull aggregation (fp16 gather, fp32 accumulate)
// ---------------------------------------------------------------------------
__global__ __launch_bounds__(256) void aggregate_kernel(const float4* __restrict__ bias4,
                                                        float* __restrict__ out) {
    int gwarp = (blockIdx.x * 256 + threadIdx.x) >> 5;
    int lane  = threadIdx.x & 31;
    int node  = gwarp * 2 + (lane >> 4);
    if (node >= N_NODES) return;
    int g = lane & 15;

    int cnt = g_degs[N_NODES + node];
    int start = g_row_start[node] - cnt;     // row_start was bumped to END by fill
    const int* ep = &g_esrc[start];

    float4 acc = make_float4(0.f, 0.f, 0.f, 0.f);
    int j = 0;
    for (; j + 8 <= cnt; j += 8) {
        uint2 r[8];
        #pragma unroll
        for (int q = 0; q < 8; q++) {
            int s = ep[j + q];
            r[q] = *(const uint2*)&g_h16[s * OUT_C + g * 4];
        }
        #pragma unroll
        for (int q = 0; q < 8; q++) {
            float2 f0 = __half22float2(*(__half2*)&r[q].x);
            float2 f1 = __half22float2(*(__half2*)&r[q].y);
            acc.x += f0.x; acc.y += f0.y; acc.z += f1.x; acc.w += f1.y;
        }
    }
    for (; j < cnt; j++) {
        int s = ep[j];
        uint2 r = *(const uint2*)&g_h16[s * OUT_C + g * 4];
        float2 f0 = __half22float2(*(__half2*)&r.x);
        float2 f1 = __half22float2(*(__half2*)&r.y);
        acc.x += f0.x; acc.y += f0.y; acc.z += f1.x; acc.w += f1.y;
    }

    float rn = rsqrtf(fmaxf((float)cnt, 1.0f));
    float4 b = bias4[g];
    float4 r;
    r.x = acc.x * rn + b.x;
    r.y = acc.y * rn + b.y;
    r.z = acc.z * rn + b.z;
    r.w = acc.w * rn + b.w;
    __stcs((float4*)&out[node * OUT_C + g * 4], r);
}

// ---------------------------------------------------------------------------
extern "C" void kernel_launch(void* const* d_in, const int* in_sizes, int n_in,
                              void* d_out, int out_size) {
    const float* x      = (const float*)d_in[0];
    const float* weight = (const float*)d_in[1];
    const float* bias   = (const float*)d_in[2];
    const int*   src    = (const int*)d_in[3];
    const int*   dst    = (const int*)d_in[4];
    float* out = (float*)d_out;

    // side stream + fork/join events (host objects only; no device allocation)
    cudaStream_t s2;
    cudaEvent_t evFork, evJoin;
    cudaStreamCreateWithFlags(&s2, cudaStreamNonBlocking);
    cudaEventCreateWithFlags(&evFork, cudaEventDisableTiming);
    cudaEventCreateWithFlags(&evJoin, cudaEventDisableTiming);

    // zero degree counters via memset node (DMA)
    void* degs_ptr = nullptr;
    cudaGetSymbolAddress(&degs_ptr, g_degs);
    cudaMemsetAsync(degs_ptr, 0, 2 * N_NODES * sizeof(int));

    degree_kernel<<<(N_EDGES / 4 + 255) / 256, 256>>>((const int4*)src, (const int4*)dst);

    // fork: CSR-build chain on s2, GEMM on main stream, concurrently
    cudaEventRecord(evFork, 0);
    cudaStreamWaitEvent(s2, evFork, 0);

    scan_block_kernel<<<N_SCAN_BLOCKS, SCAN_BLOCK, 0, s2>>>();
    add_offsets_kernel<<<N_SCAN_BLOCKS, SCAN_BLOCK, 0, s2>>>();
    csr_fill_kernel<<<(N_EDGES / 4 + 255) / 256, 256, 0, s2>>>((const int4*)src,
                                                               (const int4*)dst);
    cudaEventRecord(evJoin, s2);

    gemm_kernel<<<(N_NODES + 255) / 256, 256>>>(x, weight);

    // join: aggregate needs both g_h16 (main) and g_esrc (s2)
    cudaStreamWaitEvent(0, evJoin, 0);
    int nwarps = (N_NODES + 1) / 2;
    aggregate_kernel<<<(nwarps + 7) / 8, 256>>>((const float4*)bias, out);

    cudaEventDestroy(evFork);
    cudaEventDestroy(evJoin);
    cudaStreamDestroy(s2);
}